// round 1
// baseline (speedup 1.0000x reference)
#include <cuda_runtime.h>
#include <math.h>

// Problem constants
#define D      1024
#define D3     3072
#define D4     4096
#define TSEQ   2048
#define NBATCH 2
#define NTOK   4096    // NBATCH * TSEQ
#define NH     16
#define HD     64
#define EPS    1.1920929e-07f

// ---------------------------------------------------------------------------
// Scratch (device globals; no allocations allowed)
// ---------------------------------------------------------------------------
__device__ float g_h[NTOK * D];       // rmsnorm output (reused for both norms)
__device__ float g_qkv[NTOK * D3];    // qkv projection
__device__ float g_o[NTOK * D];       // attention output
__device__ float g_act[NTOK * D4];    // fc1+gelu output

// ---------------------------------------------------------------------------
// RMSNorm: one block per token row, 256 threads x float4
// ---------------------------------------------------------------------------
__global__ void rmsnorm_kernel(const float* __restrict__ x,
                               const float* __restrict__ g,
                               float* __restrict__ out) {
    int row = blockIdx.x;
    const float4* xr = reinterpret_cast<const float4*>(x + (size_t)row * D);
    float4 v = xr[threadIdx.x];
    float s = v.x * v.x + v.y * v.y + v.z * v.z + v.w * v.w;
    #pragma unroll
    for (int o = 16; o > 0; o >>= 1) s += __shfl_xor_sync(0xffffffffu, s, o);
    __shared__ float ws[8];
    if ((threadIdx.x & 31) == 0) ws[threadIdx.x >> 5] = s;
    __syncthreads();
    float tot = ws[0] + ws[1] + ws[2] + ws[3] + ws[4] + ws[5] + ws[6] + ws[7];
    float inv = rsqrtf(tot * (1.0f / (float)D) + EPS);
    float4 gv = reinterpret_cast<const float4*>(g)[threadIdx.x];
    float4 r;
    r.x = v.x * inv * gv.x;
    r.y = v.y * inv * gv.y;
    r.z = v.z * inv * gv.z;
    r.w = v.w * inv * gv.w;
    reinterpret_cast<float4*>(out + (size_t)row * D)[threadIdx.x] = r;
}

// ---------------------------------------------------------------------------
// Tiled SGEMM: C[M,N] = A[M,K] @ B[K,N] + bias (+ epilogue)
// BM=BN=128, BK=16, 256 threads, 8x8 per thread
// ---------------------------------------------------------------------------
#define BM 128
#define BN 128
#define BK 16

#define EPI_BIAS 0
#define EPI_GELU 1
#define EPI_RES  2

template <int EPI>
__global__ __launch_bounds__(256, 2)
void gemm_kernel(const float* __restrict__ A, const float* __restrict__ Bw,
                 const float* __restrict__ bias, const float* R,
                 float* C, int M, int N, int K) {
    __shared__ float As[BK][BM];
    __shared__ float Bs[BK][BN];
    int tid = threadIdx.x;
    int bm = blockIdx.y * BM;
    int bn = blockIdx.x * BN;
    int tx = tid & 15, ty = tid >> 4;
    int row0 = ty * 8, col0 = tx * 8;

    float acc[8][8];
    #pragma unroll
    for (int i = 0; i < 8; i++)
        #pragma unroll
        for (int j = 0; j < 8; j++) acc[i][j] = 0.0f;

    int aid0 = tid * 2;
    for (int kt = 0; kt < K; kt += BK) {
        #pragma unroll
        for (int u = 0; u < 2; u++) {
            int id = aid0 + u;
            int r = id >> 2;            // 0..127
            int k4 = (id & 3) * 4;      // 0,4,8,12
            float4 va = *reinterpret_cast<const float4*>(A + (size_t)(bm + r) * K + kt + k4);
            As[k4 + 0][r] = va.x;
            As[k4 + 1][r] = va.y;
            As[k4 + 2][r] = va.z;
            As[k4 + 3][r] = va.w;
        }
        #pragma unroll
        for (int u = 0; u < 2; u++) {
            int id = aid0 + u;
            int kk = id >> 5;           // 0..15
            int c4 = (id & 31) * 4;     // 0..124
            float4 vb = *reinterpret_cast<const float4*>(Bw + (size_t)(kt + kk) * N + bn + c4);
            *reinterpret_cast<float4*>(&Bs[kk][c4]) = vb;
        }
        __syncthreads();
        #pragma unroll
        for (int kk = 0; kk < BK; kk++) {
            float a[8], b[8];
            *reinterpret_cast<float4*>(&a[0]) = *reinterpret_cast<float4*>(&As[kk][row0]);
            *reinterpret_cast<float4*>(&a[4]) = *reinterpret_cast<float4*>(&As[kk][row0 + 4]);
            *reinterpret_cast<float4*>(&b[0]) = *reinterpret_cast<float4*>(&Bs[kk][col0]);
            *reinterpret_cast<float4*>(&b[4]) = *reinterpret_cast<float4*>(&Bs[kk][col0 + 4]);
            #pragma unroll
            for (int i = 0; i < 8; i++)
                #pragma unroll
                for (int j = 0; j < 8; j++)
                    acc[i][j] += a[i] * b[j];
        }
        __syncthreads();
    }

    float bv[8];
    *reinterpret_cast<float4*>(&bv[0]) = *reinterpret_cast<const float4*>(&bias[bn + col0]);
    *reinterpret_cast<float4*>(&bv[4]) = *reinterpret_cast<const float4*>(&bias[bn + col0 + 4]);

    #pragma unroll
    for (int i = 0; i < 8; i++) {
        size_t off = (size_t)(bm + row0 + i) * N + bn + col0;
        float outv[8];
        #pragma unroll
        for (int j = 0; j < 8; j++) {
            float v = acc[i][j] + bv[j];
            if (EPI == EPI_GELU) v = 0.5f * v * (1.0f + erff(v * 0.70710678118654752f));
            outv[j] = v;
        }
        if (EPI == EPI_RES) {
            float4 ra = *reinterpret_cast<const float4*>(&R[off]);
            float4 rb = *reinterpret_cast<const float4*>(&R[off + 4]);
            outv[0] += ra.x; outv[1] += ra.y; outv[2] += ra.z; outv[3] += ra.w;
            outv[4] += rb.x; outv[5] += rb.y; outv[6] += rb.z; outv[7] += rb.w;
        }
        float4 o0, o1;
        o0.x = outv[0]; o0.y = outv[1]; o0.z = outv[2]; o0.w = outv[3];
        o1.x = outv[4]; o1.y = outv[5]; o1.z = outv[6]; o1.w = outv[7];
        *reinterpret_cast<float4*>(&C[off])     = o0;
        *reinterpret_cast<float4*>(&C[off + 4]) = o1;
    }
}

// ---------------------------------------------------------------------------
// Flash-style causal attention.
//   logits = q.k (NO scaling);  attn = softmax(logits) * d^-0.5
// 64 q-rows per block, 64-wide K/V chunks, online softmax.
// ---------------------------------------------------------------------------
#define ASTR 68   // smem row stride (pad for float4 alignment + bank spread)
#define ATTN_SMEM (4 * 64 * ASTR * 4)

__global__ __launch_bounds__(256, 2)
void attn_kernel(const float* __restrict__ qkv, float* __restrict__ o) {
    extern __shared__ float sm[];
    float* Qt = sm;                 // [d][r] transposed
    float* Kt = Qt + 64 * ASTR;     // [d][c] transposed
    float* Vs = Kt + 64 * ASTR;     // [j][d]
    float* Ps = Vs + 64 * ASTR;     // [r][j]

    int tid = threadIdx.x;
    int tx = tid & 15, ty = tid >> 4;
    int r0 = ty * 4, c0 = tx * 4;
    int qb = blockIdx.x, h = blockIdx.y, b = blockIdx.z;
    int qbase = qb * 64;
    size_t tok0 = (size_t)b * TSEQ;

    const float* qptr = qkv + (tok0 + qbase) * D3 + h * HD;
    for (int i = tid; i < 64 * 64; i += 256) {
        int r = i >> 6, d = i & 63;
        Qt[d * ASTR + r] = qptr[(size_t)r * D3 + d];
    }

    float m[4], l[4], acc[4][4];
    #pragma unroll
    for (int i = 0; i < 4; i++) {
        m[i] = -1e30f; l[i] = 0.0f;
        #pragma unroll
        for (int j = 0; j < 4; j++) acc[i][j] = 0.0f;
    }
    __syncthreads();

    for (int kc = 0; kc <= qb; kc++) {
        int kbase = kc * 64;
        const float* kptr = qkv + (tok0 + kbase) * D3 + h * HD + D;
        const float* vptr = qkv + (tok0 + kbase) * D3 + h * HD + 2 * D;

        __syncthreads();  // previous iteration fully done with Vs/Ps
        for (int i = tid; i < 64 * 64; i += 256) {
            int r = i >> 6, d = i & 63;
            Kt[d * ASTR + r] = kptr[(size_t)r * D3 + d];
        }
        for (int i = tid * 4; i < 64 * 64; i += 1024) {
            int r = i >> 6, d = i & 63;
            *reinterpret_cast<float4*>(&Vs[r * ASTR + d]) =
                *reinterpret_cast<const float4*>(&vptr[(size_t)r * D3 + d]);
        }
        __syncthreads();

        // S = Q @ K^T (4x4 per thread)
        float s[4][4];
        #pragma unroll
        for (int i = 0; i < 4; i++)
            #pragma unroll
            for (int j = 0; j < 4; j++) s[i][j] = 0.0f;
        #pragma unroll 8
        for (int d = 0; d < 64; d++) {
            float4 aq = *reinterpret_cast<float4*>(&Qt[d * ASTR + r0]);
            float4 bk = *reinterpret_cast<float4*>(&Kt[d * ASTR + c0]);
            float aqv[4] = {aq.x, aq.y, aq.z, aq.w};
            float bkv[4] = {bk.x, bk.y, bk.z, bk.w};
            #pragma unroll
            for (int i = 0; i < 4; i++)
                #pragma unroll
                for (int j = 0; j < 4; j++)
                    s[i][j] += aqv[i] * bkv[j];
        }

        // causal mask + online softmax stats (16-lane groups share a row set)
        #pragma unroll
        for (int i = 0; i < 4; i++) {
            int qi = qbase + r0 + i;
            float mx = -1e30f;
            #pragma unroll
            for (int j = 0; j < 4; j++) {
                if (kbase + c0 + j > qi) s[i][j] = -1e30f;
                mx = fmaxf(mx, s[i][j]);
            }
            #pragma unroll
            for (int ofs = 1; ofs < 16; ofs <<= 1)
                mx = fmaxf(mx, __shfl_xor_sync(0xffffffffu, mx, ofs));
            float mn = fmaxf(m[i], mx);
            float scale = __expf(m[i] - mn);
            m[i] = mn;
            float rs = 0.0f;
            #pragma unroll
            for (int j = 0; j < 4; j++) {
                float p = __expf(s[i][j] - mn);
                s[i][j] = p;
                rs += p;
            }
            #pragma unroll
            for (int ofs = 1; ofs < 16; ofs <<= 1)
                rs += __shfl_xor_sync(0xffffffffu, rs, ofs);
            l[i] = l[i] * scale + rs;
            #pragma unroll
            for (int j = 0; j < 4; j++) acc[i][j] *= scale;
        }

        // store P
        #pragma unroll
        for (int i = 0; i < 4; i++) {
            float4 pv;
            pv.x = s[i][0]; pv.y = s[i][1]; pv.z = s[i][2]; pv.w = s[i][3];
            *reinterpret_cast<float4*>(&Ps[(r0 + i) * ASTR + c0]) = pv;
        }
        __syncthreads();

        // O += P @ V (4 rows x 4 head-dims per thread)
        #pragma unroll 8
        for (int j = 0; j < 64; j++) {
            float ap0 = Ps[(r0 + 0) * ASTR + j];
            float ap1 = Ps[(r0 + 1) * ASTR + j];
            float ap2 = Ps[(r0 + 2) * ASTR + j];
            float ap3 = Ps[(r0 + 3) * ASTR + j];
            float4 bv = *reinterpret_cast<float4*>(&Vs[j * ASTR + c0]);
            acc[0][0] += ap0 * bv.x; acc[0][1] += ap0 * bv.y; acc[0][2] += ap0 * bv.z; acc[0][3] += ap0 * bv.w;
            acc[1][0] += ap1 * bv.x; acc[1][1] += ap1 * bv.y; acc[1][2] += ap1 * bv.z; acc[1][3] += ap1 * bv.w;
            acc[2][0] += ap2 * bv.x; acc[2][1] += ap2 * bv.y; acc[2][2] += ap2 * bv.z; acc[2][3] += ap2 * bv.w;
            acc[3][0] += ap3 * bv.x; acc[3][1] += ap3 * bv.y; acc[3][2] += ap3 * bv.z; acc[3][3] += ap3 * bv.w;
        }
    }

    // normalize + the faithful-quirk d^-0.5 scale on softmax output
    float* optr = o + (tok0 + qbase) * D + h * HD;
    #pragma unroll
    for (int i = 0; i < 4; i++) {
        float inv = 0.03125f / l[i];   // 1024^-0.5 / l
        float4 r;
        r.x = acc[i][0] * inv;
        r.y = acc[i][1] * inv;
        r.z = acc[i][2] * inv;
        r.w = acc[i][3] * inv;
        *reinterpret_cast<float4*>(&optr[(size_t)(r0 + i) * D + c0]) = r;
    }
}

// ---------------------------------------------------------------------------
// Launch
// ---------------------------------------------------------------------------
extern "C" void kernel_launch(void* const* d_in, const int* in_sizes, int n_in,
                              void* d_out, int out_size) {
    const float* x      = (const float*)d_in[0];
    const float* w_attn = (const float*)d_in[1];
    const float* b_attn = (const float*)d_in[2];
    const float* w_proj = (const float*)d_in[3];
    const float* b_proj = (const float*)d_in[4];
    const float* w_fc1  = (const float*)d_in[5];
    const float* b_fc1  = (const float*)d_in[6];
    const float* w_fc2  = (const float*)d_in[7];
    const float* b_fc2  = (const float*)d_in[8];
    const float* g1     = (const float*)d_in[9];
    const float* g2     = (const float*)d_in[10];
    float* out = (float*)d_out;

    float *h, *qkvp, *op, *actp;
    cudaGetSymbolAddress((void**)&h,    g_h);
    cudaGetSymbolAddress((void**)&qkvp, g_qkv);
    cudaGetSymbolAddress((void**)&op,   g_o);
    cudaGetSymbolAddress((void**)&actp, g_act);

    cudaFuncSetAttribute(attn_kernel, cudaFuncAttributeMaxDynamicSharedMemorySize, ATTN_SMEM);

    // 1. h = rmsnorm(x, g1)
    rmsnorm_kernel<<<NTOK, 256>>>(x, g1, h);
    // 2. qkv = h @ w_attn + b_attn
    gemm_kernel<EPI_BIAS><<<dim3(D3 / BN, NTOK / BM), 256>>>(
        h, w_attn, b_attn, nullptr, qkvp, NTOK, D3, D);
    // 3. attention
    attn_kernel<<<dim3(TSEQ / 64, NH, NBATCH), 256, ATTN_SMEM>>>(qkvp, op);
    // 4. out = x + o @ w_proj + b_proj
    gemm_kernel<EPI_RES><<<dim3(D / BN, NTOK / BM), 256>>>(
        op, w_proj, b_proj, x, out, NTOK, D, D);
    // 5. h = rmsnorm(out, g2)
    rmsnorm_kernel<<<NTOK, 256>>>(out, g2, h);
    // 6. act = gelu(h @ w_fc1 + b_fc1)
    gemm_kernel<EPI_GELU><<<dim3(D4 / BN, NTOK / BM), 256>>>(
        h, w_fc1, b_fc1, nullptr, actp, NTOK, D4, D);
    // 7. out = out + act @ w_fc2 + b_fc2
    gemm_kernel<EPI_RES><<<dim3(D / BN, NTOK / BM), 256>>>(
        actp, w_fc2, b_fc2, out, out, NTOK, D, D4);
}

// round 3
// speedup vs baseline: 2.2192x; 2.2192x over previous
#include <cuda_runtime.h>
#include <cuda_bf16.h>
#include <math.h>
#include <cstdint>

#define D      1024
#define D3     3072
#define D4     4096
#define TSEQ   2048
#define NBATCH 2
#define NTOK   4096
#define NH     16
#define HD     64
#define EPS    1.1920929e-07f

// ---------------------------------------------------------------------------
// Scratch (device globals; no allocations allowed)
// ---------------------------------------------------------------------------
__device__ __nv_bfloat16 g_ah[NTOK * D];    // activation hi
__device__ __nv_bfloat16 g_al[NTOK * D];    // activation lo
__device__ __nv_bfloat16 g_bh[NTOK * D4];   // fc1 output hi
__device__ __nv_bfloat16 g_bl[NTOK * D4];   // fc1 output lo
__device__ __nv_bfloat16 g_wth[D * D4];     // transposed weight hi (shared)
__device__ __nv_bfloat16 g_wtl[D * D4];     // transposed weight lo (shared)
__device__ float g_qkv[NTOK * D3];          // qkv fp32 (attention input)

// ---------------------------------------------------------------------------
// Helpers
// ---------------------------------------------------------------------------
__device__ __forceinline__ uint32_t smem_to_u32(const void* p) {
    uint32_t a;
    asm("{ .reg .u64 t; cvta.to.shared.u64 t, %1; cvt.u32.u64 %0, t; }" : "=r"(a) : "l"(p));
    return a;
}

// chunk-xor swizzle: 16B chunk index ^= (row & 7)
#define SWZ(off) ((uint32_t)(off) ^ ((((uint32_t)(off) >> 7) & 7) << 4))

__device__ __forceinline__ void ldsm_x4(uint32_t* r, uint32_t addr) {
    asm volatile("ldmatrix.sync.aligned.m8n8.x4.shared.b16 {%0,%1,%2,%3}, [%4];"
                 : "=r"(r[0]), "=r"(r[1]), "=r"(r[2]), "=r"(r[3]) : "r"(addr));
}
__device__ __forceinline__ void ldsm_x2(uint32_t* r, uint32_t addr) {
    asm volatile("ldmatrix.sync.aligned.m8n8.x2.shared.b16 {%0,%1}, [%2];"
                 : "=r"(r[0]), "=r"(r[1]) : "r"(addr));
}
__device__ __forceinline__ void mma_bf16(float* d, const uint32_t* a, const uint32_t* b) {
    asm volatile(
        "mma.sync.aligned.m16n8k16.row.col.f32.bf16.bf16.f32 "
        "{%0,%1,%2,%3}, {%4,%5,%6,%7}, {%8,%9}, {%0,%1,%2,%3};"
        : "+f"(d[0]), "+f"(d[1]), "+f"(d[2]), "+f"(d[3])
        : "r"(a[0]), "r"(a[1]), "r"(a[2]), "r"(a[3]), "r"(b[0]), "r"(b[1]));
}

__device__ __forceinline__ void split2(float v, __nv_bfloat16& h, __nv_bfloat16& l) {
    h = __float2bfloat16(v);
    l = __float2bfloat16(v - __bfloat162float(h));
}

// ---------------------------------------------------------------------------
// RMSNorm -> bf16 hi/lo split
// ---------------------------------------------------------------------------
__global__ void rmsnorm_split_kernel(const float* __restrict__ x,
                                     const float* __restrict__ g,
                                     __nv_bfloat16* __restrict__ oh,
                                     __nv_bfloat16* __restrict__ ol) {
    int row = blockIdx.x;
    const float4* xr = reinterpret_cast<const float4*>(x + (size_t)row * D);
    float4 v = xr[threadIdx.x];
    float s = v.x * v.x + v.y * v.y + v.z * v.z + v.w * v.w;
    #pragma unroll
    for (int o = 16; o > 0; o >>= 1) s += __shfl_xor_sync(0xffffffffu, s, o);
    __shared__ float ws[8];
    if ((threadIdx.x & 31) == 0) ws[threadIdx.x >> 5] = s;
    __syncthreads();
    float tot = ws[0] + ws[1] + ws[2] + ws[3] + ws[4] + ws[5] + ws[6] + ws[7];
    float inv = rsqrtf(tot * (1.0f / (float)D) + EPS);
    float4 gv = reinterpret_cast<const float4*>(g)[threadIdx.x];
    float vals[4] = {v.x * inv * gv.x, v.y * inv * gv.y, v.z * inv * gv.z, v.w * inv * gv.w};
    __nv_bfloat16 h[4], l[4];
    #pragma unroll
    for (int j = 0; j < 4; j++) split2(vals[j], h[j], l[j]);
    size_t off = (size_t)row * D + threadIdx.x * 4;
    *reinterpret_cast<__nv_bfloat162*>(&oh[off])     = __halves2bfloat162(h[0], h[1]);
    *reinterpret_cast<__nv_bfloat162*>(&oh[off + 2]) = __halves2bfloat162(h[2], h[3]);
    *reinterpret_cast<__nv_bfloat162*>(&ol[off])     = __halves2bfloat162(l[0], l[1]);
    *reinterpret_cast<__nv_bfloat162*>(&ol[off + 2]) = __halves2bfloat162(l[2], l[3]);
}

// ---------------------------------------------------------------------------
// Weight transpose + bf16 split: W[K,N] -> Wt_hi/Wt_lo [N,K]
// ---------------------------------------------------------------------------
__global__ void transpose_split_kernel(const float* __restrict__ W, int K, int N,
                                       __nv_bfloat16* __restrict__ Th,
                                       __nv_bfloat16* __restrict__ Tl) {
    __shared__ float t[32][33];
    int k0 = blockIdx.y * 32, n0 = blockIdx.x * 32;
    int x = threadIdx.x, y = threadIdx.y;   // 32 x 8
    #pragma unroll
    for (int i = y; i < 32; i += 8)
        t[i][x] = W[(size_t)(k0 + i) * N + n0 + x];
    __syncthreads();
    #pragma unroll
    for (int b = y; b < 32; b += 8) {
        float v = t[x][b];
        __nv_bfloat16 h, l;
        split2(v, h, l);
        size_t o = (size_t)(n0 + b) * K + k0 + x;
        Th[o] = h;
        Tl[o] = l;
    }
}

// ---------------------------------------------------------------------------
// mma.sync split-bf16 GEMM: C[M,N] = (Ah+Al)@(Bh+Bl)^T + bias (+ epilogue)
// A: [M,K] bf16 hi/lo row-major. B: [N,K] bf16 hi/lo row-major.
// 128x128 tile, BK=64, 8 warps (2x4) of 64x32, double-buffered cp.async.
// ---------------------------------------------------------------------------
#define EPI_BIAS 0
#define EPI_GELU 1
#define EPI_RES  2

#define STAGE_BYTES 65536              // 4 tiles x (128 rows x 128B)
#define TCG_SMEM (2 * STAGE_BYTES)

template <int EPI>
__global__ __launch_bounds__(256, 1)
void tcgemm_kernel(const __nv_bfloat16* __restrict__ Ah, const __nv_bfloat16* __restrict__ Al,
                   const __nv_bfloat16* __restrict__ Bh, const __nv_bfloat16* __restrict__ Bl,
                   const float* __restrict__ bias, const float* __restrict__ R,
                   float* __restrict__ C,
                   __nv_bfloat16* __restrict__ Oh, __nv_bfloat16* __restrict__ Ol,
                   int M, int N, int K) {
    extern __shared__ __align__(1024) char smem[];
    uint32_t sbase = smem_to_u32(smem);
    const int tid = threadIdx.x;
    const int wid = tid >> 5, lid = tid & 31;
    const int wm = wid >> 2, wn = wid & 3;        // warp tile: 64(m) x 32(n)
    const int bm = blockIdx.y * 128, bn = blockIdx.x * 128;

    const __nv_bfloat16* srcs[4] = {Ah, Al, Bh, Bl};

    // load one 128x64 (bf16) chunk of all 4 tiles into stage s
    auto load_chunk = [&](int c, int s) {
        uint32_t tb = sbase + s * STAGE_BYTES;
        #pragma unroll
        for (int t4 = 0; t4 < 4; t4++) {
            const __nv_bfloat16* src = srcs[t4];
            int rbase = (t4 < 2) ? bm : bn;
            uint32_t dst0 = tb + t4 * 16384;
            #pragma unroll
            for (int i = 0; i < 4; i++) {
                int u = tid + i * 256;
                int r = u >> 3, j = u & 7;
                uint32_t d = dst0 + SWZ(r * 128 + j * 16);
                const void* g = src + (size_t)(rbase + r) * K + c * 64 + j * 8;
                asm volatile("cp.async.cg.shared.global [%0], [%1], 16;"
                             :: "r"(d), "l"(g) : "memory");
            }
        }
        asm volatile("cp.async.commit_group;" ::: "memory");
    };

    float acc[4][4][4];
    #pragma unroll
    for (int im = 0; im < 4; im++)
        #pragma unroll
        for (int in = 0; in < 4; in++)
            #pragma unroll
            for (int q = 0; q < 4; q++) acc[im][in][q] = 0.0f;

    const int nchunks = K >> 6;
    load_chunk(0, 0);

    // per-thread ldmatrix address components
    const int arow = wm * 64 + (lid & 15);        // A: rows of 16x16 atom
    const int acol = (lid >> 4) * 16;             // A: 16B col half
    const int brow = wn * 32 + (lid & 7);         // B: rows of 8x16 atom
    const int bcol = ((lid >> 3) & 1) * 16;       // B: 16B col half (k halves)

    for (int c = 0; c < nchunks; c++) {
        int s = c & 1;
        if (c + 1 < nchunks) {
            load_chunk(c + 1, s ^ 1);
            asm volatile("cp.async.wait_group 1;" ::: "memory");
        } else {
            asm volatile("cp.async.wait_group 0;" ::: "memory");
        }
        __syncthreads();

        uint32_t tb = sbase + s * STAGE_BYTES;
        uint32_t tAh = tb, tAl = tb + 16384, tBh = tb + 32768, tBl = tb + 49152;

        #pragma unroll
        for (int ks = 0; ks < 4; ks++) {
            uint32_t ah[4][4], al[4][4], bh[4][2], bl[4][2];
            #pragma unroll
            for (int im = 0; im < 4; im++) {
                uint32_t off = SWZ((arow + im * 16) * 128 + ks * 32 + acol);
                ldsm_x4(ah[im], tAh + off);
            }
            #pragma unroll
            for (int in = 0; in < 4; in++) {
                uint32_t off = SWZ((brow + in * 8) * 128 + ks * 32 + bcol);
                ldsm_x2(bh[in], tBh + off);
            }
            #pragma unroll
            for (int in = 0; in < 4; in++) {
                uint32_t off = SWZ((brow + in * 8) * 128 + ks * 32 + bcol);
                ldsm_x2(bl[in], tBl + off);
            }
            #pragma unroll
            for (int im = 0; im < 4; im++) {
                uint32_t off = SWZ((arow + im * 16) * 128 + ks * 32 + acol);
                ldsm_x4(al[im], tAl + off);
            }
            #pragma unroll
            for (int im = 0; im < 4; im++)
                #pragma unroll
                for (int in = 0; in < 4; in++)
                    mma_bf16(acc[im][in], ah[im], bh[in]);
            #pragma unroll
            for (int im = 0; im < 4; im++)
                #pragma unroll
                for (int in = 0; in < 4; in++)
                    mma_bf16(acc[im][in], ah[im], bl[in]);
            #pragma unroll
            for (int im = 0; im < 4; im++)
                #pragma unroll
                for (int in = 0; in < 4; in++)
                    mma_bf16(acc[im][in], al[im], bh[in]);
        }
        __syncthreads();
    }

    // ---- epilogue: accumulators live in registers ----
    #pragma unroll
    for (int im = 0; im < 4; im++) {
        #pragma unroll
        for (int in = 0; in < 4; in++) {
            int m0 = bm + wm * 64 + im * 16 + (lid >> 2);
            int n0 = bn + wn * 32 + in * 8 + (lid & 3) * 2;
            float b0 = bias[n0], b1 = bias[n0 + 1];
            #pragma unroll
            for (int half = 0; half < 2; half++) {
                int m = m0 + half * 8;
                float v0 = acc[im][in][half * 2]     + b0;
                float v1 = acc[im][in][half * 2 + 1] + b1;
                size_t off = (size_t)m * N + n0;
                if (EPI == EPI_GELU) {
                    float g0 = 0.5f * v0 * (1.0f + erff(v0 * 0.70710678118654752f));
                    float g1 = 0.5f * v1 * (1.0f + erff(v1 * 0.70710678118654752f));
                    __nv_bfloat16 h0, l0, h1, l1;
                    split2(g0, h0, l0);
                    split2(g1, h1, l1);
                    *reinterpret_cast<__nv_bfloat162*>(&Oh[off]) = __halves2bfloat162(h0, h1);
                    *reinterpret_cast<__nv_bfloat162*>(&Ol[off]) = __halves2bfloat162(l0, l1);
                } else {
                    if (EPI == EPI_RES) {
                        float2 rr = *reinterpret_cast<const float2*>(&R[off]);
                        v0 += rr.x; v1 += rr.y;
                    }
                    float2 o2 = make_float2(v0, v1);
                    *reinterpret_cast<float2*>(&C[off]) = o2;
                }
            }
        }
    }
}

// ---------------------------------------------------------------------------
// Flash-style causal attention (fp32), output written as bf16 hi/lo split.
// ---------------------------------------------------------------------------
#define ASTR 68
#define ATTN_SMEM (4 * 64 * ASTR * 4)

__global__ __launch_bounds__(256, 2)
void attn_kernel(const float* __restrict__ qkv,
                 __nv_bfloat16* __restrict__ oh, __nv_bfloat16* __restrict__ ol) {
    extern __shared__ float sm[];
    float* Qt = sm;
    float* Kt = Qt + 64 * ASTR;
    float* Vs = Kt + 64 * ASTR;
    float* Ps = Vs + 64 * ASTR;

    int tid = threadIdx.x;
    int tx = tid & 15, ty = tid >> 4;
    int r0 = ty * 4, c0 = tx * 4;
    int qb = blockIdx.x, h = blockIdx.y, b = blockIdx.z;
    int qbase = qb * 64;
    size_t tok0 = (size_t)b * TSEQ;

    const float* qptr = qkv + (tok0 + qbase) * D3 + h * HD;
    for (int i = tid; i < 64 * 64; i += 256) {
        int r = i >> 6, d = i & 63;
        Qt[d * ASTR + r] = qptr[(size_t)r * D3 + d];
    }

    float m[4], l[4], acc[4][4];
    #pragma unroll
    for (int i = 0; i < 4; i++) {
        m[i] = -1e30f; l[i] = 0.0f;
        #pragma unroll
        for (int j = 0; j < 4; j++) acc[i][j] = 0.0f;
    }
    __syncthreads();

    for (int kc = 0; kc <= qb; kc++) {
        int kbase = kc * 64;
        const float* kptr = qkv + (tok0 + kbase) * D3 + h * HD + D;
        const float* vptr = qkv + (tok0 + kbase) * D3 + h * HD + 2 * D;

        __syncthreads();
        for (int i = tid; i < 64 * 64; i += 256) {
            int r = i >> 6, d = i & 63;
            Kt[d * ASTR + r] = kptr[(size_t)r * D3 + d];
        }
        for (int i = tid * 4; i < 64 * 64; i += 1024) {
            int r = i >> 6, d = i & 63;
            *reinterpret_cast<float4*>(&Vs[r * ASTR + d]) =
                *reinterpret_cast<const float4*>(&vptr[(size_t)r * D3 + d]);
        }
        __syncthreads();

        float s[4][4];
        #pragma unroll
        for (int i = 0; i < 4; i++)
            #pragma unroll
            for (int j = 0; j < 4; j++) s[i][j] = 0.0f;
        #pragma unroll 8
        for (int d = 0; d < 64; d++) {
            float4 aq = *reinterpret_cast<float4*>(&Qt[d * ASTR + r0]);
            float4 bk = *reinterpret_cast<float4*>(&Kt[d * ASTR + c0]);
            float aqv[4] = {aq.x, aq.y, aq.z, aq.w};
            float bkv[4] = {bk.x, bk.y, bk.z, bk.w};
            #pragma unroll
            for (int i = 0; i < 4; i++)
                #pragma unroll
                for (int j = 0; j < 4; j++)
                    s[i][j] += aqv[i] * bkv[j];
        }

        #pragma unroll
        for (int i = 0; i < 4; i++) {
            int qi = qbase + r0 + i;
            float mx = -1e30f;
            #pragma unroll
            for (int j = 0; j < 4; j++) {
                if (kbase + c0 + j > qi) s[i][j] = -1e30f;
                mx = fmaxf(mx, s[i][j]);
            }
            #pragma unroll
            for (int ofs = 1; ofs < 16; ofs <<= 1)
                mx = fmaxf(mx, __shfl_xor_sync(0xffffffffu, mx, ofs));
            float mn = fmaxf(m[i], mx);
            float scale = __expf(m[i] - mn);
            m[i] = mn;
            float rs = 0.0f;
            #pragma unroll
            for (int j = 0; j < 4; j++) {
                float p = __expf(s[i][j] - mn);
                s[i][j] = p;
                rs += p;
            }
            #pragma unroll
            for (int ofs = 1; ofs < 16; ofs <<= 1)
                rs += __shfl_xor_sync(0xffffffffu, rs, ofs);
            l[i] = l[i] * scale + rs;
            #pragma unroll
            for (int j = 0; j < 4; j++) acc[i][j] *= scale;
        }

        #pragma unroll
        for (int i = 0; i < 4; i++) {
            float4 pv;
            pv.x = s[i][0]; pv.y = s[i][1]; pv.z = s[i][2]; pv.w = s[i][3];
            *reinterpret_cast<float4*>(&Ps[(r0 + i) * ASTR + c0]) = pv;
        }
        __syncthreads();

        #pragma unroll 8
        for (int j = 0; j < 64; j++) {
            float ap0 = Ps[(r0 + 0) * ASTR + j];
            float ap1 = Ps[(r0 + 1) * ASTR + j];
            float ap2 = Ps[(r0 + 2) * ASTR + j];
            float ap3 = Ps[(r0 + 3) * ASTR + j];
            float4 bv = *reinterpret_cast<float4*>(&Vs[j * ASTR + c0]);
            acc[0][0] += ap0 * bv.x; acc[0][1] += ap0 * bv.y; acc[0][2] += ap0 * bv.z; acc[0][3] += ap0 * bv.w;
            acc[1][0] += ap1 * bv.x; acc[1][1] += ap1 * bv.y; acc[1][2] += ap1 * bv.z; acc[1][3] += ap1 * bv.w;
            acc[2][0] += ap2 * bv.x; acc[2][1] += ap2 * bv.y; acc[2][2] += ap2 * bv.z; acc[2][3] += ap2 * bv.w;
            acc[3][0] += ap3 * bv.x; acc[3][1] += ap3 * bv.y; acc[3][2] += ap3 * bv.z; acc[3][3] += ap3 * bv.w;
        }
    }

    // normalize + quirk d^-0.5 scale; write bf16 hi/lo split
    #pragma unroll
    for (int i = 0; i < 4; i++) {
        float inv = 0.03125f / l[i];   // 1024^-0.5 / l
        size_t off = (tok0 + qbase + r0 + i) * (size_t)D + h * HD + c0;
        __nv_bfloat16 hh[4], ll[4];
        split2(acc[i][0] * inv, hh[0], ll[0]);
        split2(acc[i][1] * inv, hh[1], ll[1]);
        split2(acc[i][2] * inv, hh[2], ll[2]);
        split2(acc[i][3] * inv, hh[3], ll[3]);
        *reinterpret_cast<__nv_bfloat162*>(&oh[off])     = __halves2bfloat162(hh[0], hh[1]);
        *reinterpret_cast<__nv_bfloat162*>(&oh[off + 2]) = __halves2bfloat162(hh[2], hh[3]);
        *reinterpret_cast<__nv_bfloat162*>(&ol[off])     = __halves2bfloat162(ll[0], ll[1]);
        *reinterpret_cast<__nv_bfloat162*>(&ol[off + 2]) = __halves2bfloat162(ll[2], ll[3]);
    }
}

// ---------------------------------------------------------------------------
// Launch
// ---------------------------------------------------------------------------
extern "C" void kernel_launch(void* const* d_in, const int* in_sizes, int n_in,
                              void* d_out, int out_size) {
    const float* x      = (const float*)d_in[0];
    const float* w_attn = (const float*)d_in[1];
    const float* b_attn = (const float*)d_in[2];
    const float* w_proj = (const float*)d_in[3];
    const float* b_proj = (const float*)d_in[4];
    const float* w_fc1  = (const float*)d_in[5];
    const float* b_fc1  = (const float*)d_in[6];
    const float* w_fc2  = (const float*)d_in[7];
    const float* b_fc2  = (const float*)d_in[8];
    const float* g1     = (const float*)d_in[9];
    const float* g2     = (const float*)d_in[10];
    float* out = (float*)d_out;

    __nv_bfloat16 *ah, *al, *bh, *bl, *wth, *wtl;
    float* qkvp;
    cudaGetSymbolAddress((void**)&ah,  g_ah);
    cudaGetSymbolAddress((void**)&al,  g_al);
    cudaGetSymbolAddress((void**)&bh,  g_bh);
    cudaGetSymbolAddress((void**)&bl,  g_bl);
    cudaGetSymbolAddress((void**)&wth, g_wth);
    cudaGetSymbolAddress((void**)&wtl, g_wtl);
    cudaGetSymbolAddress((void**)&qkvp, g_qkv);

    cudaFuncSetAttribute(attn_kernel, cudaFuncAttributeMaxDynamicSharedMemorySize, ATTN_SMEM);
    cudaFuncSetAttribute(tcgemm_kernel<EPI_BIAS>, cudaFuncAttributeMaxDynamicSharedMemorySize, TCG_SMEM);
    cudaFuncSetAttribute(tcgemm_kernel<EPI_GELU>, cudaFuncAttributeMaxDynamicSharedMemorySize, TCG_SMEM);
    cudaFuncSetAttribute(tcgemm_kernel<EPI_RES>,  cudaFuncAttributeMaxDynamicSharedMemorySize, TCG_SMEM);

    dim3 tp(32, 8);

    // 1. rmsnorm(x, g1) -> ah/al
    rmsnorm_split_kernel<<<NTOK, 256>>>(x, g1, ah, al);
    // 2. qkv = h @ w_attn + b_attn   (fp32 output)
    transpose_split_kernel<<<dim3(D3 / 32, D / 32), tp>>>(w_attn, D, D3, wth, wtl);
    tcgemm_kernel<EPI_BIAS><<<dim3(D3 / 128, NTOK / 128), 256, TCG_SMEM>>>(
        ah, al, wth, wtl, b_attn, nullptr, qkvp, nullptr, nullptr, NTOK, D3, D);
    // 3. attention -> ah/al
    attn_kernel<<<dim3(TSEQ / 64, NH, NBATCH), 256, ATTN_SMEM>>>(qkvp, ah, al);
    // 4. out = x + o @ w_proj + b_proj
    transpose_split_kernel<<<dim3(D / 32, D / 32), tp>>>(w_proj, D, D, wth, wtl);
    tcgemm_kernel<EPI_RES><<<dim3(D / 128, NTOK / 128), 256, TCG_SMEM>>>(
        ah, al, wth, wtl, b_proj, x, out, nullptr, nullptr, NTOK, D, D);
    // 5. rmsnorm(out, g2) -> ah/al
    rmsnorm_split_kernel<<<NTOK, 256>>>(out, g2, ah, al);
    // 6. bh/bl = gelu(h @ w_fc1 + b_fc1) split
    transpose_split_kernel<<<dim3(D4 / 32, D / 32), tp>>>(w_fc1, D, D4, wth, wtl);
    tcgemm_kernel<EPI_GELU><<<dim3(D4 / 128, NTOK / 128), 256, TCG_SMEM>>>(
        ah, al, wth, wtl, b_fc1, nullptr, nullptr, bh, bl, NTOK, D4, D);
    // 7. out = out + act @ w_fc2 + b_fc2
    transpose_split_kernel<<<dim3(D / 32, D4 / 32), tp>>>(w_fc2, D4, D, wth, wtl);
    tcgemm_kernel<EPI_RES><<<dim3(D / 128, NTOK / 128), 256, TCG_SMEM>>>(
        bh, bl, wth, wtl, b_fc2, out, out, nullptr, nullptr, NTOK, D, D4);
}

// round 5
// speedup vs baseline: 3.0706x; 1.3837x over previous
#include <cuda_runtime.h>
#include <cuda_bf16.h>
#include <math.h>
#include <cstdint>

#define D      1024
#define D3     3072
#define D4     4096
#define TSEQ   2048
#define NBATCH 2
#define NTOK   4096
#define NH     16
#define HD     64
#define EPS    1.1920929e-07f

// ---------------------------------------------------------------------------
// Scratch (device globals; no allocations allowed)
// ---------------------------------------------------------------------------
__device__ __nv_bfloat16 g_ah[NTOK * D];    // activation hi
__device__ __nv_bfloat16 g_al[NTOK * D];    // activation lo
__device__ __nv_bfloat16 g_bh[NTOK * D4];   // fc1 output hi
__device__ __nv_bfloat16 g_bl[NTOK * D4];   // fc1 output lo
__device__ __nv_bfloat16 g_wth[D * D4];     // transposed weight hi (shared)
__device__ __nv_bfloat16 g_wtl[D * D4];     // transposed weight lo (shared)
__device__ float g_qkv[NTOK * D3];          // qkv fp32 (attention input)

// ---------------------------------------------------------------------------
// Helpers
// ---------------------------------------------------------------------------
__device__ __forceinline__ uint32_t smem_to_u32(const void* p) {
    uint32_t a;
    asm("{ .reg .u64 t; cvta.to.shared.u64 t, %1; cvt.u32.u64 %0, t; }" : "=r"(a) : "l"(p));
    return a;
}

// chunk-xor swizzle: 16B chunk index ^= (row & 7)
#define SWZ(off) ((uint32_t)(off) ^ ((((uint32_t)(off) >> 7) & 7) << 4))

__device__ __forceinline__ void ldsm_x4(uint32_t* r, uint32_t addr) {
    asm volatile("ldmatrix.sync.aligned.m8n8.x4.shared.b16 {%0,%1,%2,%3}, [%4];"
                 : "=r"(r[0]), "=r"(r[1]), "=r"(r[2]), "=r"(r[3]) : "r"(addr));
}
__device__ __forceinline__ void ldsm_x2(uint32_t* r, uint32_t addr) {
    asm volatile("ldmatrix.sync.aligned.m8n8.x2.shared.b16 {%0,%1}, [%2];"
                 : "=r"(r[0]), "=r"(r[1]) : "r"(addr));
}
__device__ __forceinline__ void ldsm_x2_trans(uint32_t* r, uint32_t addr) {
    asm volatile("ldmatrix.sync.aligned.m8n8.x2.trans.shared.b16 {%0,%1}, [%2];"
                 : "=r"(r[0]), "=r"(r[1]) : "r"(addr));
}
__device__ __forceinline__ void mma_bf16_g(float* d, const uint32_t* a, const uint32_t* b) {
    asm volatile(
        "mma.sync.aligned.m16n8k16.row.col.f32.bf16.bf16.f32 "
        "{%0,%1,%2,%3}, {%4,%5,%6,%7}, {%8,%9}, {%0,%1,%2,%3};"
        : "+f"(d[0]), "+f"(d[1]), "+f"(d[2]), "+f"(d[3])
        : "r"(a[0]), "r"(a[1]), "r"(a[2]), "r"(a[3]), "r"(b[0]), "r"(b[1]));
}

__device__ __forceinline__ void split2(float v, __nv_bfloat16& h, __nv_bfloat16& l) {
    h = __float2bfloat16(v);
    l = __float2bfloat16(v - __bfloat162float(h));
}

// pack bf16x2: lo half = cvt(a), hi half = cvt(b)
__device__ __forceinline__ uint32_t pack_bf16x2(float a, float b) {
    uint32_t r;
    asm("cvt.rn.bf16x2.f32 %0, %1, %2;" : "=r"(r) : "f"(b), "f"(a));
    return r;
}
// take hi16 of two fp32 -> packed bf16x2 (truncation split)
__device__ __forceinline__ uint32_t pack_hi16(float a, float b) {
    uint32_t r;
    asm("prmt.b32 %0, %1, %2, 0x7632;" : "=r"(r) : "r"(__float_as_uint(a)), "r"(__float_as_uint(b)));
    return r;
}
__device__ __forceinline__ float trunc_bf16f(float v) {
    return __uint_as_float(__float_as_uint(v) & 0xFFFF0000u);
}

// ---------------------------------------------------------------------------
// RMSNorm -> bf16 hi/lo split
// ---------------------------------------------------------------------------
__global__ void rmsnorm_split_kernel(const float* __restrict__ x,
                                     const float* __restrict__ g,
                                     __nv_bfloat16* __restrict__ oh,
                                     __nv_bfloat16* __restrict__ ol) {
    int row = blockIdx.x;
    const float4* xr = reinterpret_cast<const float4*>(x + (size_t)row * D);
    float4 v = xr[threadIdx.x];
    float s = v.x * v.x + v.y * v.y + v.z * v.z + v.w * v.w;
    #pragma unroll
    for (int o = 16; o > 0; o >>= 1) s += __shfl_xor_sync(0xffffffffu, s, o);
    __shared__ float ws[8];
    if ((threadIdx.x & 31) == 0) ws[threadIdx.x >> 5] = s;
    __syncthreads();
    float tot = ws[0] + ws[1] + ws[2] + ws[3] + ws[4] + ws[5] + ws[6] + ws[7];
    float inv = rsqrtf(tot * (1.0f / (float)D) + EPS);
    float4 gv = reinterpret_cast<const float4*>(g)[threadIdx.x];
    float vals[4] = {v.x * inv * gv.x, v.y * inv * gv.y, v.z * inv * gv.z, v.w * inv * gv.w};
    __nv_bfloat16 h[4], l[4];
    #pragma unroll
    for (int j = 0; j < 4; j++) split2(vals[j], h[j], l[j]);
    size_t off = (size_t)row * D + threadIdx.x * 4;
    *reinterpret_cast<__nv_bfloat162*>(&oh[off])     = __halves2bfloat162(h[0], h[1]);
    *reinterpret_cast<__nv_bfloat162*>(&oh[off + 2]) = __halves2bfloat162(h[2], h[3]);
    *reinterpret_cast<__nv_bfloat162*>(&ol[off])     = __halves2bfloat162(l[0], l[1]);
    *reinterpret_cast<__nv_bfloat162*>(&ol[off + 2]) = __halves2bfloat162(l[2], l[3]);
}

// ---------------------------------------------------------------------------
// Weight transpose + bf16 split: W[K,N] -> Wt_hi/Wt_lo [N,K]
// ---------------------------------------------------------------------------
__global__ void transpose_split_kernel(const float* __restrict__ W, int K, int N,
                                       __nv_bfloat16* __restrict__ Th,
                                       __nv_bfloat16* __restrict__ Tl) {
    __shared__ float t[32][33];
    int k0 = blockIdx.y * 32, n0 = blockIdx.x * 32;
    int x = threadIdx.x, y = threadIdx.y;   // 32 x 8
    #pragma unroll
    for (int i = y; i < 32; i += 8)
        t[i][x] = W[(size_t)(k0 + i) * N + n0 + x];
    __syncthreads();
    #pragma unroll
    for (int b = y; b < 32; b += 8) {
        float v = t[x][b];
        __nv_bfloat16 h, l;
        split2(v, h, l);
        size_t o = (size_t)(n0 + b) * K + k0 + x;
        Th[o] = h;
        Tl[o] = l;
    }
}

// ---------------------------------------------------------------------------
// mma.sync split-bf16 GEMM (unchanged from R3, verified at 3.5e-6)
// ---------------------------------------------------------------------------
#define EPI_BIAS 0
#define EPI_GELU 1
#define EPI_RES  2

#define STAGE_BYTES 65536
#define TCG_SMEM (2 * STAGE_BYTES)

template <int EPI>
__global__ __launch_bounds__(256, 1)
void tcgemm_kernel(const __nv_bfloat16* __restrict__ Ah, const __nv_bfloat16* __restrict__ Al,
                   const __nv_bfloat16* __restrict__ Bh, const __nv_bfloat16* __restrict__ Bl,
                   const float* __restrict__ bias, const float* __restrict__ R,
                   float* __restrict__ C,
                   __nv_bfloat16* __restrict__ Oh, __nv_bfloat16* __restrict__ Ol,
                   int M, int N, int K) {
    extern __shared__ __align__(1024) char smem[];
    uint32_t sbase = smem_to_u32(smem);
    const int tid = threadIdx.x;
    const int wid = tid >> 5, lid = tid & 31;
    const int wm = wid >> 2, wn = wid & 3;
    const int bm = blockIdx.y * 128, bn = blockIdx.x * 128;

    const __nv_bfloat16* srcs[4] = {Ah, Al, Bh, Bl};

    auto load_chunk = [&](int c, int s) {
        uint32_t tb = sbase + s * STAGE_BYTES;
        #pragma unroll
        for (int t4 = 0; t4 < 4; t4++) {
            const __nv_bfloat16* src = srcs[t4];
            int rbase = (t4 < 2) ? bm : bn;
            uint32_t dst0 = tb + t4 * 16384;
            #pragma unroll
            for (int i = 0; i < 4; i++) {
                int u = tid + i * 256;
                int r = u >> 3, j = u & 7;
                uint32_t d = dst0 + SWZ(r * 128 + j * 16);
                const void* g = src + (size_t)(rbase + r) * K + c * 64 + j * 8;
                asm volatile("cp.async.cg.shared.global [%0], [%1], 16;"
                             :: "r"(d), "l"(g) : "memory");
            }
        }
        asm volatile("cp.async.commit_group;" ::: "memory");
    };

    float acc[4][4][4];
    #pragma unroll
    for (int im = 0; im < 4; im++)
        #pragma unroll
        for (int in = 0; in < 4; in++)
            #pragma unroll
            for (int q = 0; q < 4; q++) acc[im][in][q] = 0.0f;

    const int nchunks = K >> 6;
    load_chunk(0, 0);

    const int arow = wm * 64 + (lid & 15);
    const int acol = (lid >> 4) * 16;
    const int brow = wn * 32 + (lid & 7);
    const int bcol = ((lid >> 3) & 1) * 16;

    for (int c = 0; c < nchunks; c++) {
        int s = c & 1;
        if (c + 1 < nchunks) {
            load_chunk(c + 1, s ^ 1);
            asm volatile("cp.async.wait_group 1;" ::: "memory");
        } else {
            asm volatile("cp.async.wait_group 0;" ::: "memory");
        }
        __syncthreads();

        uint32_t tb = sbase + s * STAGE_BYTES;
        uint32_t tAh = tb, tAl = tb + 16384, tBh = tb + 32768, tBl = tb + 49152;

        #pragma unroll
        for (int ks = 0; ks < 4; ks++) {
            uint32_t ah[4][4], al[4][4], bh[4][2], bl[4][2];
            #pragma unroll
            for (int im = 0; im < 4; im++) {
                uint32_t off = SWZ((arow + im * 16) * 128 + ks * 32 + acol);
                ldsm_x4(ah[im], tAh + off);
            }
            #pragma unroll
            for (int in = 0; in < 4; in++) {
                uint32_t off = SWZ((brow + in * 8) * 128 + ks * 32 + bcol);
                ldsm_x2(bh[in], tBh + off);
            }
            #pragma unroll
            for (int in = 0; in < 4; in++) {
                uint32_t off = SWZ((brow + in * 8) * 128 + ks * 32 + bcol);
                ldsm_x2(bl[in], tBl + off);
            }
            #pragma unroll
            for (int im = 0; im < 4; im++) {
                uint32_t off = SWZ((arow + im * 16) * 128 + ks * 32 + acol);
                ldsm_x4(al[im], tAl + off);
            }
            #pragma unroll
            for (int im = 0; im < 4; im++)
                #pragma unroll
                for (int in = 0; in < 4; in++)
                    mma_bf16_g(acc[im][in], ah[im], bh[in]);
            #pragma unroll
            for (int im = 0; im < 4; im++)
                #pragma unroll
                for (int in = 0; in < 4; in++)
                    mma_bf16_g(acc[im][in], ah[im], bl[in]);
            #pragma unroll
            for (int im = 0; im < 4; im++)
                #pragma unroll
                for (int in = 0; in < 4; in++)
                    mma_bf16_g(acc[im][in], al[im], bh[in]);
        }
        __syncthreads();
    }

    #pragma unroll
    for (int im = 0; im < 4; im++) {
        #pragma unroll
        for (int in = 0; in < 4; in++) {
            int m0 = bm + wm * 64 + im * 16 + (lid >> 2);
            int n0 = bn + wn * 32 + in * 8 + (lid & 3) * 2;
            float b0 = bias[n0], b1 = bias[n0 + 1];
            #pragma unroll
            for (int half = 0; half < 2; half++) {
                int m = m0 + half * 8;
                float v0 = acc[im][in][half * 2]     + b0;
                float v1 = acc[im][in][half * 2 + 1] + b1;
                size_t off = (size_t)m * N + n0;
                if (EPI == EPI_GELU) {
                    float g0 = 0.5f * v0 * (1.0f + erff(v0 * 0.70710678118654752f));
                    float g1 = 0.5f * v1 * (1.0f + erff(v1 * 0.70710678118654752f));
                    __nv_bfloat16 h0, l0, h1, l1;
                    split2(g0, h0, l0);
                    split2(g1, h1, l1);
                    *reinterpret_cast<__nv_bfloat162*>(&Oh[off]) = __halves2bfloat162(h0, h1);
                    *reinterpret_cast<__nv_bfloat162*>(&Ol[off]) = __halves2bfloat162(l0, l1);
                } else {
                    if (EPI == EPI_RES) {
                        float2 rr = *reinterpret_cast<const float2*>(&R[off]);
                        v0 += rr.x; v1 += rr.y;
                    }
                    float2 o2 = make_float2(v0, v1);
                    *reinterpret_cast<float2*>(&C[off]) = o2;
                }
            }
        }
    }
}

// ---------------------------------------------------------------------------
// Tensor-core flash attention.
// CTA = 128 q-rows x 1 head. 8 warps, 16 rows each. K/V chunks of 64.
// S = QK^T and O += PV via m16n8k16 with split-bf16 3-pass.
// logits NOT scaled; softmax output scaled by d^-0.5 (faithful quirk).
// ---------------------------------------------------------------------------
#define ATTN_SMEM 65536

__global__ __launch_bounds__(256, 1)
void attn_mma_kernel(const float* __restrict__ qkv,
                     __nv_bfloat16* __restrict__ oh, __nv_bfloat16* __restrict__ ol) {
    extern __shared__ __align__(1024) char smem_raw[];
    uint32_t sb = smem_to_u32(smem_raw);
    const uint32_t sQh = 0, sQl = 16384, sKh = 32768, sKl = 40960, sVh = 49152, sVl = 57344;

    const int tid = threadIdx.x;
    const int wid = tid >> 5, lid = tid & 31;
    const int qb = blockIdx.x, h = blockIdx.y, b = blockIdx.z;
    const int qbase = qb * 128;
    const size_t tok0 = (size_t)b * TSEQ;

    // ---- load Q (128x64 fp32 -> split bf16 smem) ----
    {
        const float* qptr = qkv + (tok0 + qbase) * D3 + h * HD;
        #pragma unroll
        for (int i = 0; i < 8; i++) {
            int idx = tid + i * 256;
            int r = idx >> 4, d4 = (idx & 15) * 4;
            float4 v = *reinterpret_cast<const float4*>(qptr + (size_t)r * D3 + d4);
            __nv_bfloat16 hh[4], ll[4];
            split2(v.x, hh[0], ll[0]); split2(v.y, hh[1], ll[1]);
            split2(v.z, hh[2], ll[2]); split2(v.w, hh[3], ll[3]);
            uint32_t o = SWZ(r * 128 + d4 * 2);
            *reinterpret_cast<__nv_bfloat162*>(smem_raw + sQh + o)     = __halves2bfloat162(hh[0], hh[1]);
            *reinterpret_cast<__nv_bfloat162*>(smem_raw + sQh + o + 4) = __halves2bfloat162(hh[2], hh[3]);
            *reinterpret_cast<__nv_bfloat162*>(smem_raw + sQl + o)     = __halves2bfloat162(ll[0], ll[1]);
            *reinterpret_cast<__nv_bfloat162*>(smem_raw + sQl + o + 4) = __halves2bfloat162(ll[2], ll[3]);
        }
    }

    float mrow[2] = {-1e30f, -1e30f};
    float lrow[2] = {0.0f, 0.0f};
    float oacc[8][4];
    #pragma unroll
    for (int t = 0; t < 8; t++)
        #pragma unroll
        for (int c = 0; c < 4; c++) oacc[t][c] = 0.0f;

    const int nchunks = 2 * qb + 2;
    const int wrow_hi = qbase + 16 * wid + 15;   // highest row this warp owns

    for (int kc = 0; kc < nchunks; kc++) {
        const int kbase = kc * 64;
        __syncthreads();   // previous compute done before K/V overwrite
        {
            const float* kp = qkv + (tok0 + kbase) * D3 + h * HD + D;
            const float* vp = qkv + (tok0 + kbase) * D3 + h * HD + 2 * D;
            #pragma unroll
            for (int i = 0; i < 4; i++) {
                int idx = tid + i * 256;
                int r = idx >> 4, d4 = (idx & 15) * 4;
                uint32_t o = SWZ(r * 128 + d4 * 2);
                float4 kv4 = *reinterpret_cast<const float4*>(kp + (size_t)r * D3 + d4);
                __nv_bfloat16 hh[4], ll[4];
                split2(kv4.x, hh[0], ll[0]); split2(kv4.y, hh[1], ll[1]);
                split2(kv4.z, hh[2], ll[2]); split2(kv4.w, hh[3], ll[3]);
                *reinterpret_cast<__nv_bfloat162*>(smem_raw + sKh + o)     = __halves2bfloat162(hh[0], hh[1]);
                *reinterpret_cast<__nv_bfloat162*>(smem_raw + sKh + o + 4) = __halves2bfloat162(hh[2], hh[3]);
                *reinterpret_cast<__nv_bfloat162*>(smem_raw + sKl + o)     = __halves2bfloat162(ll[0], ll[1]);
                *reinterpret_cast<__nv_bfloat162*>(smem_raw + sKl + o + 4) = __halves2bfloat162(ll[2], ll[3]);
                float4 vv4 = *reinterpret_cast<const float4*>(vp + (size_t)r * D3 + d4);
                split2(vv4.x, hh[0], ll[0]); split2(vv4.y, hh[1], ll[1]);
                split2(vv4.z, hh[2], ll[2]); split2(vv4.w, hh[3], ll[3]);
                *reinterpret_cast<__nv_bfloat162*>(smem_raw + sVh + o)     = __halves2bfloat162(hh[0], hh[1]);
                *reinterpret_cast<__nv_bfloat162*>(smem_raw + sVh + o + 4) = __halves2bfloat162(hh[2], hh[3]);
                *reinterpret_cast<__nv_bfloat162*>(smem_raw + sVl + o)     = __halves2bfloat162(ll[0], ll[1]);
                *reinterpret_cast<__nv_bfloat162*>(smem_raw + sVl + o + 4) = __halves2bfloat162(ll[2], ll[3]);
            }
        }
        __syncthreads();

        if (wrow_hi < kbase) continue;   // warp fully masked for this chunk

        // ---- S = Q K^T (split 3-pass) ----
        uint32_t qh[4][4], ql[4][4];
        {
            int qr = 16 * wid + (lid & 15);
            int qc = (lid >> 4) * 16;
            #pragma unroll
            for (int ks = 0; ks < 4; ks++) {
                uint32_t off = SWZ(qr * 128 + ks * 32 + qc);
                ldsm_x4(qh[ks], sb + sQh + off);
                ldsm_x4(ql[ks], sb + sQl + off);
            }
        }
        float sacc[8][4];
        #pragma unroll
        for (int t = 0; t < 8; t++)
            #pragma unroll
            for (int c = 0; c < 4; c++) sacc[t][c] = 0.0f;

        {
            int kr = lid & 7;
            int kcb = ((lid >> 3) & 1) * 16;
            #pragma unroll
            for (int t = 0; t < 8; t++) {
                #pragma unroll
                for (int ks = 0; ks < 4; ks++) {
                    uint32_t off = SWZ((t * 8 + kr) * 128 + ks * 32 + kcb);
                    uint32_t bh2[2], bl2[2];
                    ldsm_x2(bh2, sb + sKh + off);
                    ldsm_x2(bl2, sb + sKl + off);
                    mma_bf16_g(sacc[t], qh[ks], bh2);
                    mma_bf16_g(sacc[t], ql[ks], bh2);
                    mma_bf16_g(sacc[t], qh[ks], bl2);
                }
            }
        }

        // ---- causal mask (only the two diagonal chunks) ----
        if (kc >= 2 * qb) {
            int row0 = qbase + 16 * wid + (lid >> 2);
            #pragma unroll
            for (int t = 0; t < 8; t++) {
                int col = kbase + t * 8 + 2 * (lid & 3);
                if (col > row0)     sacc[t][0] = -1e30f;
                if (col + 1 > row0) sacc[t][1] = -1e30f;
                if (col > row0 + 8)     sacc[t][2] = -1e30f;
                if (col + 1 > row0 + 8) sacc[t][3] = -1e30f;
            }
        }

        // ---- online softmax (rows owned by quad; shfl 1,2 covers cols) ----
        #pragma unroll
        for (int rr = 0; rr < 2; rr++) {
            float mx = -1e30f;
            #pragma unroll
            for (int t = 0; t < 8; t++)
                mx = fmaxf(mx, fmaxf(sacc[t][2 * rr], sacc[t][2 * rr + 1]));
            mx = fmaxf(mx, __shfl_xor_sync(0xffffffffu, mx, 1));
            mx = fmaxf(mx, __shfl_xor_sync(0xffffffffu, mx, 2));
            float mn = fmaxf(mrow[rr], mx);
            float sc = __expf(mrow[rr] - mn);
            mrow[rr] = mn;
            float rs = 0.0f;
            #pragma unroll
            for (int t = 0; t < 8; t++) {
                float p0 = __expf(sacc[t][2 * rr] - mn);
                float p1 = __expf(sacc[t][2 * rr + 1] - mn);
                sacc[t][2 * rr] = p0; sacc[t][2 * rr + 1] = p1;
                rs += p0 + p1;
            }
            lrow[rr] = lrow[rr] * sc + rs;
            #pragma unroll
            for (int t = 0; t < 8; t++) {
                oacc[t][2 * rr]     *= sc;
                oacc[t][2 * rr + 1] *= sc;
            }
        }

        // ---- O += P V (split 3-pass; P truncation-split) ----
        {
            int vr = (lid & 7) + ((lid >> 3) & 1) * 8;
            #pragma unroll
            for (int j = 0; j < 4; j++) {
                uint32_t ph[4], pl[4];
                #pragma unroll
                for (int half = 0; half < 2; half++) {   // tiles 2j, 2j+1
                    float a0 = sacc[2 * j + half][0], a1 = sacc[2 * j + half][1];
                    float a2 = sacc[2 * j + half][2], a3 = sacc[2 * j + half][3];
                    ph[0 + 2 * half] = pack_hi16(a0, a1);
                    ph[1 + 2 * half] = pack_hi16(a2, a3);
                    pl[0 + 2 * half] = pack_bf16x2(a0 - trunc_bf16f(a0), a1 - trunc_bf16f(a1));
                    pl[1 + 2 * half] = pack_bf16x2(a2 - trunc_bf16f(a2), a3 - trunc_bf16f(a3));
                }
                // A-fragment convention:
                //   ph[0]=tile2j rows r (k 0..7), ph[1]=tile2j rows r+8,
                //   ph[2]=tile2j+1 rows r (k 8..15), ph[3]=tile2j+1 rows r+8
                #pragma unroll
                for (int t = 0; t < 8; t++) {
                    uint32_t voff = SWZ((j * 16 + vr) * 128 + t * 16);
                    uint32_t vh2[2], vl2[2];
                    ldsm_x2_trans(vh2, sb + sVh + voff);
                    ldsm_x2_trans(vl2, sb + sVl + voff);
                    mma_bf16_g(oacc[t], ph, vh2);
                    mma_bf16_g(oacc[t], pl, vh2);
                    mma_bf16_g(oacc[t], ph, vl2);
                }
            }
        }
    }

    // ---- finalize: quad-reduce l, scale by 1/(32 l), write split bf16 ----
    lrow[0] += __shfl_xor_sync(0xffffffffu, lrow[0], 1);
    lrow[0] += __shfl_xor_sync(0xffffffffu, lrow[0], 2);
    lrow[1] += __shfl_xor_sync(0xffffffffu, lrow[1], 1);
    lrow[1] += __shfl_xor_sync(0xffffffffu, lrow[1], 2);
    float inv0 = 0.03125f / lrow[0];
    float inv1 = 0.03125f / lrow[1];

    #pragma unroll
    for (int rr = 0; rr < 2; rr++) {
        float inv = rr ? inv1 : inv0;
        int row = qbase + 16 * wid + (lid >> 2) + rr * 8;
        size_t base = (tok0 + row) * (size_t)D + h * HD + 2 * (lid & 3);
        #pragma unroll
        for (int t = 0; t < 8; t++) {
            float v0 = oacc[t][2 * rr] * inv;
            float v1 = oacc[t][2 * rr + 1] * inv;
            __nv_bfloat16 h0, l0, h1, l1;
            split2(v0, h0, l0);
            split2(v1, h1, l1);
            *reinterpret_cast<__nv_bfloat162*>(&oh[base + t * 8]) = __halves2bfloat162(h0, h1);
            *reinterpret_cast<__nv_bfloat162*>(&ol[base + t * 8]) = __halves2bfloat162(l0, l1);
        }
    }
}

// ---------------------------------------------------------------------------
// Launch
// ---------------------------------------------------------------------------
extern "C" void kernel_launch(void* const* d_in, const int* in_sizes, int n_in,
                              void* d_out, int out_size) {
    const float* x      = (const float*)d_in[0];
    const float* w_attn = (const float*)d_in[1];
    const float* b_attn = (const float*)d_in[2];
    const float* w_proj = (const float*)d_in[3];
    const float* b_proj = (const float*)d_in[4];
    const float* w_fc1  = (const float*)d_in[5];
    const float* b_fc1  = (const float*)d_in[6];
    const float* w_fc2  = (const float*)d_in[7];
    const float* b_fc2  = (const float*)d_in[8];
    const float* g1     = (const float*)d_in[9];
    const float* g2     = (const float*)d_in[10];
    float* out = (float*)d_out;

    __nv_bfloat16 *ah, *al, *bh, *bl, *wth, *wtl;
    float* qkvp;
    cudaGetSymbolAddress((void**)&ah,  g_ah);
    cudaGetSymbolAddress((void**)&al,  g_al);
    cudaGetSymbolAddress((void**)&bh,  g_bh);
    cudaGetSymbolAddress((void**)&bl,  g_bl);
    cudaGetSymbolAddress((void**)&wth, g_wth);
    cudaGetSymbolAddress((void**)&wtl, g_wtl);
    cudaGetSymbolAddress((void**)&qkvp, g_qkv);

    cudaFuncSetAttribute(attn_mma_kernel, cudaFuncAttributeMaxDynamicSharedMemorySize, ATTN_SMEM);
    cudaFuncSetAttribute(tcgemm_kernel<EPI_BIAS>, cudaFuncAttributeMaxDynamicSharedMemorySize, TCG_SMEM);
    cudaFuncSetAttribute(tcgemm_kernel<EPI_GELU>, cudaFuncAttributeMaxDynamicSharedMemorySize, TCG_SMEM);
    cudaFuncSetAttribute(tcgemm_kernel<EPI_RES>,  cudaFuncAttributeMaxDynamicSharedMemorySize, TCG_SMEM);

    dim3 tp(32, 8);

    // 1. rmsnorm(x, g1) -> ah/al
    rmsnorm_split_kernel<<<NTOK, 256>>>(x, g1, ah, al);
    // 2. qkv = h @ w_attn + b_attn   (fp32 output)
    transpose_split_kernel<<<dim3(D3 / 32, D / 32), tp>>>(w_attn, D, D3, wth, wtl);
    tcgemm_kernel<EPI_BIAS><<<dim3(D3 / 128, NTOK / 128), 256, TCG_SMEM>>>(
        ah, al, wth, wtl, b_attn, nullptr, qkvp, nullptr, nullptr, NTOK, D3, D);
    // 3. attention -> ah/al
    attn_mma_kernel<<<dim3(TSEQ / 128, NH, NBATCH), 256, ATTN_SMEM>>>(qkvp, ah, al);
    // 4. out = x + o @ w_proj + b_proj
    transpose_split_kernel<<<dim3(D / 32, D / 32), tp>>>(w_proj, D, D, wth, wtl);
    tcgemm_kernel<EPI_RES><<<dim3(D / 128, NTOK / 128), 256, TCG_SMEM>>>(
        ah, al, wth, wtl, b_proj, x, out, nullptr, nullptr, NTOK, D, D);
    // 5. rmsnorm(out, g2) -> ah/al
    rmsnorm_split_kernel<<<NTOK, 256>>>(out, g2, ah, al);
    // 6. bh/bl = gelu(h @ w_fc1 + b_fc1) split
    transpose_split_kernel<<<dim3(D4 / 32, D / 32), tp>>>(w_fc1, D, D4, wth, wtl);
    tcgemm_kernel<EPI_GELU><<<dim3(D4 / 128, NTOK / 128), 256, TCG_SMEM>>>(
        ah, al, wth, wtl, b_fc1, nullptr, nullptr, bh, bl, NTOK, D4, D);
    // 7. out = out + act @ w_fc2 + b_fc2
    transpose_split_kernel<<<dim3(D / 32, D4 / 32), tp>>>(w_fc2, D4, D, wth, wtl);
    tcgemm_kernel<EPI_RES><<<dim3(D / 128, NTOK / 128), 256, TCG_SMEM>>>(
        bh, bl, wth, wtl, b_fc2, out, out, nullptr, nullptr, NTOK, D, D4);
}

// round 6
// speedup vs baseline: 3.1546x; 1.0273x over previous
#include <cuda_runtime.h>
#include <cuda_bf16.h>
#include <math.h>
#include <cstdint>

#define D      1024
#define D3     3072
#define D4     4096
#define TSEQ   2048
#define NBATCH 2
#define NTOK   4096
#define NH     16
#define HD     64
#define EPS    1.1920929e-07f

// ---------------------------------------------------------------------------
// Scratch (device globals; no allocations allowed)
// ---------------------------------------------------------------------------
__device__ __nv_bfloat16 g_ah[NTOK * D];    // activation hi
__device__ __nv_bfloat16 g_al[NTOK * D];    // activation lo
__device__ __nv_bfloat16 g_bh[NTOK * D4];   // fc1 output hi
__device__ __nv_bfloat16 g_bl[NTOK * D4];   // fc1 output lo
__device__ __nv_bfloat16 g_wth[D * D4];     // transposed weight hi (shared)
__device__ __nv_bfloat16 g_wtl[D * D4];     // transposed weight lo (shared)
// pre-split q/k/v, layout [b, h, t, d] (row = 64 bf16 = 128B)
__device__ __nv_bfloat16 g_qh[NTOK * D];
__device__ __nv_bfloat16 g_ql[NTOK * D];
__device__ __nv_bfloat16 g_kh[NTOK * D];
__device__ __nv_bfloat16 g_kl[NTOK * D];
__device__ __nv_bfloat16 g_vh[NTOK * D];
__device__ __nv_bfloat16 g_vl[NTOK * D];

// ---------------------------------------------------------------------------
// Helpers
// ---------------------------------------------------------------------------
__device__ __forceinline__ uint32_t smem_to_u32(const void* p) {
    uint32_t a;
    asm("{ .reg .u64 t; cvta.to.shared.u64 t, %1; cvt.u32.u64 %0, t; }" : "=r"(a) : "l"(p));
    return a;
}

// chunk-xor swizzle: 16B chunk index ^= (row & 7)
#define SWZ(off) ((uint32_t)(off) ^ ((((uint32_t)(off) >> 7) & 7) << 4))

__device__ __forceinline__ void ldsm_x4(uint32_t* r, uint32_t addr) {
    asm volatile("ldmatrix.sync.aligned.m8n8.x4.shared.b16 {%0,%1,%2,%3}, [%4];"
                 : "=r"(r[0]), "=r"(r[1]), "=r"(r[2]), "=r"(r[3]) : "r"(addr));
}
__device__ __forceinline__ void ldsm_x2(uint32_t* r, uint32_t addr) {
    asm volatile("ldmatrix.sync.aligned.m8n8.x2.shared.b16 {%0,%1}, [%2];"
                 : "=r"(r[0]), "=r"(r[1]) : "r"(addr));
}
__device__ __forceinline__ void ldsm_x2_trans(uint32_t* r, uint32_t addr) {
    asm volatile("ldmatrix.sync.aligned.m8n8.x2.trans.shared.b16 {%0,%1}, [%2];"
                 : "=r"(r[0]), "=r"(r[1]) : "r"(addr));
}
__device__ __forceinline__ void mma_bf16_g(float* d, const uint32_t* a, const uint32_t* b) {
    asm volatile(
        "mma.sync.aligned.m16n8k16.row.col.f32.bf16.bf16.f32 "
        "{%0,%1,%2,%3}, {%4,%5,%6,%7}, {%8,%9}, {%0,%1,%2,%3};"
        : "+f"(d[0]), "+f"(d[1]), "+f"(d[2]), "+f"(d[3])
        : "r"(a[0]), "r"(a[1]), "r"(a[2]), "r"(a[3]), "r"(b[0]), "r"(b[1]));
}

__device__ __forceinline__ void split2(float v, __nv_bfloat16& h, __nv_bfloat16& l) {
    h = __float2bfloat16(v);
    l = __float2bfloat16(v - __bfloat162float(h));
}
__device__ __forceinline__ uint32_t pack_bf16x2(float a, float b) {
    uint32_t r;
    asm("cvt.rn.bf16x2.f32 %0, %1, %2;" : "=r"(r) : "f"(b), "f"(a));
    return r;
}
__device__ __forceinline__ uint32_t pack_hi16(float a, float b) {
    uint32_t r;
    asm("prmt.b32 %0, %1, %2, 0x7632;" : "=r"(r) : "r"(__float_as_uint(a)), "r"(__float_as_uint(b)));
    return r;
}
__device__ __forceinline__ float trunc_bf16f(float v) {
    return __uint_as_float(__float_as_uint(v) & 0xFFFF0000u);
}

// ---------------------------------------------------------------------------
// RMSNorm -> bf16 hi/lo split
// ---------------------------------------------------------------------------
__global__ void rmsnorm_split_kernel(const float* __restrict__ x,
                                     const float* __restrict__ g,
                                     __nv_bfloat16* __restrict__ oh,
                                     __nv_bfloat16* __restrict__ ol) {
    int row = blockIdx.x;
    const float4* xr = reinterpret_cast<const float4*>(x + (size_t)row * D);
    float4 v = xr[threadIdx.x];
    float s = v.x * v.x + v.y * v.y + v.z * v.z + v.w * v.w;
    #pragma unroll
    for (int o = 16; o > 0; o >>= 1) s += __shfl_xor_sync(0xffffffffu, s, o);
    __shared__ float ws[8];
    if ((threadIdx.x & 31) == 0) ws[threadIdx.x >> 5] = s;
    __syncthreads();
    float tot = ws[0] + ws[1] + ws[2] + ws[3] + ws[4] + ws[5] + ws[6] + ws[7];
    float inv = rsqrtf(tot * (1.0f / (float)D) + EPS);
    float4 gv = reinterpret_cast<const float4*>(g)[threadIdx.x];
    float vals[4] = {v.x * inv * gv.x, v.y * inv * gv.y, v.z * inv * gv.z, v.w * inv * gv.w};
    __nv_bfloat16 h[4], l[4];
    #pragma unroll
    for (int j = 0; j < 4; j++) split2(vals[j], h[j], l[j]);
    size_t off = (size_t)row * D + threadIdx.x * 4;
    *reinterpret_cast<__nv_bfloat162*>(&oh[off])     = __halves2bfloat162(h[0], h[1]);
    *reinterpret_cast<__nv_bfloat162*>(&oh[off + 2]) = __halves2bfloat162(h[2], h[3]);
    *reinterpret_cast<__nv_bfloat162*>(&ol[off])     = __halves2bfloat162(l[0], l[1]);
    *reinterpret_cast<__nv_bfloat162*>(&ol[off + 2]) = __halves2bfloat162(l[2], l[3]);
}

// ---------------------------------------------------------------------------
// Weight transpose + bf16 split: W[K,N] -> Wt_hi/Wt_lo [N,K]
// ---------------------------------------------------------------------------
__global__ void transpose_split_kernel(const float* __restrict__ W, int K, int N,
                                       __nv_bfloat16* __restrict__ Th,
                                       __nv_bfloat16* __restrict__ Tl) {
    __shared__ float t[32][33];
    int k0 = blockIdx.y * 32, n0 = blockIdx.x * 32;
    int x = threadIdx.x, y = threadIdx.y;   // 32 x 8
    #pragma unroll
    for (int i = y; i < 32; i += 8)
        t[i][x] = W[(size_t)(k0 + i) * N + n0 + x];
    __syncthreads();
    #pragma unroll
    for (int b = y; b < 32; b += 8) {
        float v = t[x][b];
        __nv_bfloat16 h, l;
        split2(v, h, l);
        size_t o = (size_t)(n0 + b) * K + k0 + x;
        Th[o] = h;
        Tl[o] = l;
    }
}

// ---------------------------------------------------------------------------
// mma.sync split-bf16 GEMM, 3-stage cp.async pipeline.
// EPI_QKV writes split q/k/v to per-head [b,h,t,d] arrays.
// ---------------------------------------------------------------------------
#define EPI_BIAS 0
#define EPI_GELU 1
#define EPI_RES  2
#define EPI_QKV  3

#define STAGE_BYTES 65536
#define TCG_SMEM (3 * STAGE_BYTES)

template <int EPI>
__global__ __launch_bounds__(256, 1)
void tcgemm_kernel(const __nv_bfloat16* __restrict__ Ah, const __nv_bfloat16* __restrict__ Al,
                   const __nv_bfloat16* __restrict__ Bh, const __nv_bfloat16* __restrict__ Bl,
                   const float* __restrict__ bias, const float* __restrict__ R,
                   float* __restrict__ C,
                   __nv_bfloat16* __restrict__ Oh, __nv_bfloat16* __restrict__ Ol,
                   __nv_bfloat16* __restrict__ Qh, __nv_bfloat16* __restrict__ Ql,
                   __nv_bfloat16* __restrict__ Kh, __nv_bfloat16* __restrict__ Kl,
                   __nv_bfloat16* __restrict__ Vh, __nv_bfloat16* __restrict__ Vl,
                   int M, int N, int K) {
    extern __shared__ __align__(1024) char smem[];
    uint32_t sbase = smem_to_u32(smem);
    const int tid = threadIdx.x;
    const int wid = tid >> 5, lid = tid & 31;
    const int wm = wid >> 2, wn = wid & 3;
    const int bm = blockIdx.y * 128, bn = blockIdx.x * 128;

    const __nv_bfloat16* srcs[4] = {Ah, Al, Bh, Bl};

    auto load_chunk = [&](int c, int s) {
        uint32_t tb = sbase + s * STAGE_BYTES;
        #pragma unroll
        for (int t4 = 0; t4 < 4; t4++) {
            const __nv_bfloat16* src = srcs[t4];
            int rbase = (t4 < 2) ? bm : bn;
            uint32_t dst0 = tb + t4 * 16384;
            #pragma unroll
            for (int i = 0; i < 4; i++) {
                int u = tid + i * 256;
                int r = u >> 3, j = u & 7;
                uint32_t d = dst0 + SWZ(r * 128 + j * 16);
                const void* g = src + (size_t)(rbase + r) * K + c * 64 + j * 8;
                asm volatile("cp.async.cg.shared.global [%0], [%1], 16;"
                             :: "r"(d), "l"(g) : "memory");
            }
        }
        asm volatile("cp.async.commit_group;" ::: "memory");
    };

    float acc[4][4][4];
    #pragma unroll
    for (int im = 0; im < 4; im++)
        #pragma unroll
        for (int in = 0; in < 4; in++)
            #pragma unroll
            for (int q = 0; q < 4; q++) acc[im][in][q] = 0.0f;

    const int nchunks = K >> 6;
    load_chunk(0, 0);
    if (nchunks > 1) load_chunk(1, 1);

    const int arow = wm * 64 + (lid & 15);
    const int acol = (lid >> 4) * 16;
    const int brow = wn * 32 + (lid & 7);
    const int bcol = ((lid >> 3) & 1) * 16;

    for (int c = 0; c < nchunks; c++) {
        int s = c % 3;
        if (c + 2 < nchunks) {
            load_chunk(c + 2, (c + 2) % 3);
            asm volatile("cp.async.wait_group 2;" ::: "memory");
        } else if (c + 1 < nchunks) {
            asm volatile("cp.async.wait_group 1;" ::: "memory");
        } else {
            asm volatile("cp.async.wait_group 0;" ::: "memory");
        }
        __syncthreads();

        uint32_t tb = sbase + s * STAGE_BYTES;
        uint32_t tAh = tb, tAl = tb + 16384, tBh = tb + 32768, tBl = tb + 49152;

        #pragma unroll
        for (int ks = 0; ks < 4; ks++) {
            uint32_t ah[4][4], al[4][4], bh[4][2], bl[4][2];
            #pragma unroll
            for (int im = 0; im < 4; im++) {
                uint32_t off = SWZ((arow + im * 16) * 128 + ks * 32 + acol);
                ldsm_x4(ah[im], tAh + off);
            }
            #pragma unroll
            for (int in = 0; in < 4; in++) {
                uint32_t off = SWZ((brow + in * 8) * 128 + ks * 32 + bcol);
                ldsm_x2(bh[in], tBh + off);
            }
            #pragma unroll
            for (int in = 0; in < 4; in++) {
                uint32_t off = SWZ((brow + in * 8) * 128 + ks * 32 + bcol);
                ldsm_x2(bl[in], tBl + off);
            }
            #pragma unroll
            for (int im = 0; im < 4; im++) {
                uint32_t off = SWZ((arow + im * 16) * 128 + ks * 32 + acol);
                ldsm_x4(al[im], tAl + off);
            }
            #pragma unroll
            for (int im = 0; im < 4; im++)
                #pragma unroll
                for (int in = 0; in < 4; in++)
                    mma_bf16_g(acc[im][in], ah[im], bh[in]);
            #pragma unroll
            for (int im = 0; im < 4; im++)
                #pragma unroll
                for (int in = 0; in < 4; in++)
                    mma_bf16_g(acc[im][in], ah[im], bl[in]);
            #pragma unroll
            for (int im = 0; im < 4; im++)
                #pragma unroll
                for (int in = 0; in < 4; in++)
                    mma_bf16_g(acc[im][in], al[im], bh[in]);
        }
        __syncthreads();
    }

    #pragma unroll
    for (int im = 0; im < 4; im++) {
        #pragma unroll
        for (int in = 0; in < 4; in++) {
            int m0 = bm + wm * 64 + im * 16 + (lid >> 2);
            int n0 = bn + wn * 32 + in * 8 + (lid & 3) * 2;
            float b0 = bias[n0], b1 = bias[n0 + 1];
            #pragma unroll
            for (int half = 0; half < 2; half++) {
                int m = m0 + half * 8;
                float v0 = acc[im][in][half * 2]     + b0;
                float v1 = acc[im][in][half * 2 + 1] + b1;
                if (EPI == EPI_QKV) {
                    // m -> (b,t); n0 -> (part, head, d). write split bf16.
                    int part = n0 >> 10;
                    int head = (n0 >> 6) & 15;
                    int d = n0 & 63;
                    int bb = m >> 11, t = m & 2047;
                    size_t dst = ((size_t)(bb * NH + head) * TSEQ + t) * HD + d;
                    __nv_bfloat16 h0, l0, h1, l1;
                    split2(v0, h0, l0);
                    split2(v1, h1, l1);
                    __nv_bfloat16* dh = (part == 0) ? Qh : (part == 1) ? Kh : Vh;
                    __nv_bfloat16* dl = (part == 0) ? Ql : (part == 1) ? Kl : Vl;
                    *reinterpret_cast<__nv_bfloat162*>(&dh[dst]) = __halves2bfloat162(h0, h1);
                    *reinterpret_cast<__nv_bfloat162*>(&dl[dst]) = __halves2bfloat162(l0, l1);
                } else if (EPI == EPI_GELU) {
                    size_t off = (size_t)m * N + n0;
                    float g0 = 0.5f * v0 * (1.0f + erff(v0 * 0.70710678118654752f));
                    float g1 = 0.5f * v1 * (1.0f + erff(v1 * 0.70710678118654752f));
                    __nv_bfloat16 h0, l0, h1, l1;
                    split2(g0, h0, l0);
                    split2(g1, h1, l1);
                    *reinterpret_cast<__nv_bfloat162*>(&Oh[off]) = __halves2bfloat162(h0, h1);
                    *reinterpret_cast<__nv_bfloat162*>(&Ol[off]) = __halves2bfloat162(l0, l1);
                } else {
                    size_t off = (size_t)m * N + n0;
                    if (EPI == EPI_RES) {
                        float2 rr = *reinterpret_cast<const float2*>(&R[off]);
                        v0 += rr.x; v1 += rr.y;
                    }
                    float2 o2 = make_float2(v0, v1);
                    *reinterpret_cast<float2*>(&C[off]) = o2;
                }
            }
        }
    }
}

// ---------------------------------------------------------------------------
// Tensor-core flash attention, pre-split inputs, double-buffered cp.async K/V.
// CTA = 128 q-rows x 1 head. 8 warps, 16 rows each. K/V chunks of 64 rows.
// ---------------------------------------------------------------------------
// smem: Qh 16K | Ql 16K | slot0 {Kh,Kl,Vh,Vl} 32K | slot1 32K  = 96K
#define ATTN_SMEM 98304

__global__ __launch_bounds__(256, 1)
void attn_mma_kernel(const __nv_bfloat16* __restrict__ Qh, const __nv_bfloat16* __restrict__ Ql,
                     const __nv_bfloat16* __restrict__ Kh, const __nv_bfloat16* __restrict__ Kl,
                     const __nv_bfloat16* __restrict__ Vh, const __nv_bfloat16* __restrict__ Vl,
                     __nv_bfloat16* __restrict__ oh, __nv_bfloat16* __restrict__ ol) {
    extern __shared__ __align__(1024) char smem_raw[];
    uint32_t sb = smem_to_u32(smem_raw);
    const uint32_t sQh = 0, sQl = 16384;

    const int tid = threadIdx.x;
    const int wid = tid >> 5, lid = tid & 31;
    const int qb = blockIdx.x, h = blockIdx.y, b = blockIdx.z;
    const int qbase = qb * 128;
    const size_t hdbase = (size_t)(b * NH + h) * TSEQ * HD;

    const __nv_bfloat16* kvsrc[4] = {Kh + hdbase, Kl + hdbase, Vh + hdbase, Vl + hdbase};

    // K/V chunk loader: 64 rows x 128B x 4 tiles into slot s
    auto load_kv = [&](int c, int s) {
        uint32_t slot = sb + 32768 + s * 32768;
        int rowbase = c * 64;
        #pragma unroll
        for (int i = 0; i < 8; i++) {
            int u = tid + i * 256;              // 0..2047
            int t4 = u >> 9;                    // tile
            int c2 = u & 511;
            int r = c2 >> 3, j = c2 & 7;
            uint32_t d = slot + t4 * 8192 + SWZ(r * 128 + j * 16);
            const void* g = kvsrc[t4] + (size_t)(rowbase + r) * HD + j * 8;
            asm volatile("cp.async.cg.shared.global [%0], [%1], 16;"
                         :: "r"(d), "l"(g) : "memory");
        }
    };

    // ---- Q load (128 rows x 128B, hi+lo) + first K/V chunk, one group ----
    {
        const __nv_bfloat16* qhp = Qh + hdbase + (size_t)qbase * HD;
        const __nv_bfloat16* qlp = Ql + hdbase + (size_t)qbase * HD;
        #pragma unroll
        for (int i = 0; i < 4; i++) {
            int u = tid + i * 256;              // 0..1023
            int r = u >> 3, j = u & 7;
            uint32_t o = SWZ(r * 128 + j * 16);
            asm volatile("cp.async.cg.shared.global [%0], [%1], 16;"
                         :: "r"(sb + sQh + o), "l"((const void*)(qhp + (size_t)r * HD + j * 8)) : "memory");
            asm volatile("cp.async.cg.shared.global [%0], [%1], 16;"
                         :: "r"(sb + sQl + o), "l"((const void*)(qlp + (size_t)r * HD + j * 8)) : "memory");
        }
        load_kv(0, 0);
        asm volatile("cp.async.commit_group;" ::: "memory");
    }

    float mrow[2] = {-1e30f, -1e30f};
    float lrow[2] = {0.0f, 0.0f};
    float oacc[8][4];
    #pragma unroll
    for (int t = 0; t < 8; t++)
        #pragma unroll
        for (int c = 0; c < 4; c++) oacc[t][c] = 0.0f;

    const int nchunks = 2 * qb + 2;
    const int wrow_hi = qbase + 16 * wid + 15;

    for (int kc = 0; kc < nchunks; kc++) {
        const int kbase = kc * 64;
        const int s = kc & 1;
        if (kc + 1 < nchunks) {
            load_kv(kc + 1, s ^ 1);
            asm volatile("cp.async.commit_group;" ::: "memory");
            asm volatile("cp.async.wait_group 1;" ::: "memory");
        } else {
            asm volatile("cp.async.wait_group 0;" ::: "memory");
        }
        __syncthreads();

        if (wrow_hi >= kbase) {
            const uint32_t slot = sb + 32768 + s * 32768;
            const uint32_t tKh = slot, tKl = slot + 8192, tVh = slot + 16384, tVl = slot + 24576;

            // ---- S = Q K^T (split 3-pass) ----
            uint32_t qh[4][4], ql[4][4];
            {
                int qr = 16 * wid + (lid & 15);
                int qc = (lid >> 4) * 16;
                #pragma unroll
                for (int ks = 0; ks < 4; ks++) {
                    uint32_t off = SWZ(qr * 128 + ks * 32 + qc);
                    ldsm_x4(qh[ks], sb + sQh + off);
                    ldsm_x4(ql[ks], sb + sQl + off);
                }
            }
            float sacc[8][4];
            #pragma unroll
            for (int t = 0; t < 8; t++)
                #pragma unroll
                for (int c = 0; c < 4; c++) sacc[t][c] = 0.0f;

            {
                int kr = lid & 7;
                int kcb = ((lid >> 3) & 1) * 16;
                #pragma unroll
                for (int t = 0; t < 8; t++) {
                    #pragma unroll
                    for (int ks = 0; ks < 4; ks++) {
                        uint32_t off = SWZ((t * 8 + kr) * 128 + ks * 32 + kcb);
                        uint32_t bh2[2], bl2[2];
                        ldsm_x2(bh2, tKh + off);
                        ldsm_x2(bl2, tKl + off);
                        mma_bf16_g(sacc[t], qh[ks], bh2);
                        mma_bf16_g(sacc[t], ql[ks], bh2);
                        mma_bf16_g(sacc[t], qh[ks], bl2);
                    }
                }
            }

            // ---- causal mask (diagonal chunks only) ----
            if (kc >= 2 * qb) {
                int row0 = qbase + 16 * wid + (lid >> 2);
                #pragma unroll
                for (int t = 0; t < 8; t++) {
                    int col = kbase + t * 8 + 2 * (lid & 3);
                    if (col > row0)     sacc[t][0] = -1e30f;
                    if (col + 1 > row0) sacc[t][1] = -1e30f;
                    if (col > row0 + 8)     sacc[t][2] = -1e30f;
                    if (col + 1 > row0 + 8) sacc[t][3] = -1e30f;
                }
            }

            // ---- online softmax ----
            #pragma unroll
            for (int rr = 0; rr < 2; rr++) {
                float mx = -1e30f;
                #pragma unroll
                for (int t = 0; t < 8; t++)
                    mx = fmaxf(mx, fmaxf(sacc[t][2 * rr], sacc[t][2 * rr + 1]));
                mx = fmaxf(mx, __shfl_xor_sync(0xffffffffu, mx, 1));
                mx = fmaxf(mx, __shfl_xor_sync(0xffffffffu, mx, 2));
                float mn = fmaxf(mrow[rr], mx);
                float sc = __expf(mrow[rr] - mn);
                mrow[rr] = mn;
                float rs = 0.0f;
                #pragma unroll
                for (int t = 0; t < 8; t++) {
                    float p0 = __expf(sacc[t][2 * rr] - mn);
                    float p1 = __expf(sacc[t][2 * rr + 1] - mn);
                    sacc[t][2 * rr] = p0; sacc[t][2 * rr + 1] = p1;
                    rs += p0 + p1;
                }
                lrow[rr] = lrow[rr] * sc + rs;
                #pragma unroll
                for (int t = 0; t < 8; t++) {
                    oacc[t][2 * rr]     *= sc;
                    oacc[t][2 * rr + 1] *= sc;
                }
            }

            // ---- O += P V (split 3-pass; P truncation-split) ----
            {
                int vr = (lid & 7) + ((lid >> 3) & 1) * 8;
                #pragma unroll
                for (int j = 0; j < 4; j++) {
                    uint32_t ph[4], pl[4];
                    #pragma unroll
                    for (int half = 0; half < 2; half++) {
                        float a0 = sacc[2 * j + half][0], a1 = sacc[2 * j + half][1];
                        float a2 = sacc[2 * j + half][2], a3 = sacc[2 * j + half][3];
                        ph[0 + 2 * half] = pack_hi16(a0, a1);
                        ph[1 + 2 * half] = pack_hi16(a2, a3);
                        pl[0 + 2 * half] = pack_bf16x2(a0 - trunc_bf16f(a0), a1 - trunc_bf16f(a1));
                        pl[1 + 2 * half] = pack_bf16x2(a2 - trunc_bf16f(a2), a3 - trunc_bf16f(a3));
                    }
                    #pragma unroll
                    for (int t = 0; t < 8; t++) {
                        uint32_t voff = SWZ((j * 16 + vr) * 128 + t * 16);
                        uint32_t vh2[2], vl2[2];
                        ldsm_x2_trans(vh2, tVh + voff);
                        ldsm_x2_trans(vl2, tVl + voff);
                        mma_bf16_g(oacc[t], ph, vh2);
                        mma_bf16_g(oacc[t], pl, vh2);
                        mma_bf16_g(oacc[t], ph, vl2);
                    }
                }
            }
        }
        __syncthreads();
    }

    // ---- finalize ----
    lrow[0] += __shfl_xor_sync(0xffffffffu, lrow[0], 1);
    lrow[0] += __shfl_xor_sync(0xffffffffu, lrow[0], 2);
    lrow[1] += __shfl_xor_sync(0xffffffffu, lrow[1], 1);
    lrow[1] += __shfl_xor_sync(0xffffffffu, lrow[1], 2);
    float inv0 = 0.03125f / lrow[0];
    float inv1 = 0.03125f / lrow[1];

    const size_t tok0 = (size_t)b * TSEQ;
    #pragma unroll
    for (int rr = 0; rr < 2; rr++) {
        float inv = rr ? inv1 : inv0;
        int row = qbase + 16 * wid + (lid >> 2) + rr * 8;
        size_t base = (tok0 + row) * (size_t)D + h * HD + 2 * (lid & 3);
        #pragma unroll
        for (int t = 0; t < 8; t++) {
            float v0 = oacc[t][2 * rr] * inv;
            float v1 = oacc[t][2 * rr + 1] * inv;
            __nv_bfloat16 h0, l0, h1, l1;
            split2(v0, h0, l0);
            split2(v1, h1, l1);
            *reinterpret_cast<__nv_bfloat162*>(&oh[base + t * 8]) = __halves2bfloat162(h0, h1);
            *reinterpret_cast<__nv_bfloat162*>(&ol[base + t * 8]) = __halves2bfloat162(l0, l1);
        }
    }
}

// ---------------------------------------------------------------------------
// Launch
// ---------------------------------------------------------------------------
extern "C" void kernel_launch(void* const* d_in, const int* in_sizes, int n_in,
                              void* d_out, int out_size) {
    const float* x      = (const float*)d_in[0];
    const float* w_attn = (const float*)d_in[1];
    const float* b_attn = (const float*)d_in[2];
    const float* w_proj = (const float*)d_in[3];
    const float* b_proj = (const float*)d_in[4];
    const float* w_fc1  = (const float*)d_in[5];
    const float* b_fc1  = (const float*)d_in[6];
    const float* w_fc2  = (const float*)d_in[7];
    const float* b_fc2  = (const float*)d_in[8];
    const float* g1     = (const float*)d_in[9];
    const float* g2     = (const float*)d_in[10];
    float* out = (float*)d_out;

    __nv_bfloat16 *ah, *al, *bh, *bl, *wth, *wtl;
    __nv_bfloat16 *qh, *ql, *kh, *kl, *vh, *vl;
    cudaGetSymbolAddress((void**)&ah,  g_ah);
    cudaGetSymbolAddress((void**)&al,  g_al);
    cudaGetSymbolAddress((void**)&bh,  g_bh);
    cudaGetSymbolAddress((void**)&bl,  g_bl);
    cudaGetSymbolAddress((void**)&wth, g_wth);
    cudaGetSymbolAddress((void**)&wtl, g_wtl);
    cudaGetSymbolAddress((void**)&qh,  g_qh);
    cudaGetSymbolAddress((void**)&ql,  g_ql);
    cudaGetSymbolAddress((void**)&kh,  g_kh);
    cudaGetSymbolAddress((void**)&kl,  g_kl);
    cudaGetSymbolAddress((void**)&vh,  g_vh);
    cudaGetSymbolAddress((void**)&vl,  g_vl);

    cudaFuncSetAttribute(attn_mma_kernel, cudaFuncAttributeMaxDynamicSharedMemorySize, ATTN_SMEM);
    cudaFuncSetAttribute(tcgemm_kernel<EPI_BIAS>, cudaFuncAttributeMaxDynamicSharedMemorySize, TCG_SMEM);
    cudaFuncSetAttribute(tcgemm_kernel<EPI_GELU>, cudaFuncAttributeMaxDynamicSharedMemorySize, TCG_SMEM);
    cudaFuncSetAttribute(tcgemm_kernel<EPI_RES>,  cudaFuncAttributeMaxDynamicSharedMemorySize, TCG_SMEM);
    cudaFuncSetAttribute(tcgemm_kernel<EPI_QKV>,  cudaFuncAttributeMaxDynamicSharedMemorySize, TCG_SMEM);

    dim3 tp(32, 8);

    // 1. rmsnorm(x, g1) -> ah/al
    rmsnorm_split_kernel<<<NTOK, 256>>>(x, g1, ah, al);
    // 2. qkv gemm -> pre-split q/k/v per head
    transpose_split_kernel<<<dim3(D3 / 32, D / 32), tp>>>(w_attn, D, D3, wth, wtl);
    tcgemm_kernel<EPI_QKV><<<dim3(D3 / 128, NTOK / 128), 256, TCG_SMEM>>>(
        ah, al, wth, wtl, b_attn, nullptr, nullptr, nullptr, nullptr,
        qh, ql, kh, kl, vh, vl, NTOK, D3, D);
    // 3. attention -> ah/al
    attn_mma_kernel<<<dim3(TSEQ / 128, NH, NBATCH), 256, ATTN_SMEM>>>(
        qh, ql, kh, kl, vh, vl, ah, al);
    // 4. out = x + o @ w_proj + b_proj
    transpose_split_kernel<<<dim3(D / 32, D / 32), tp>>>(w_proj, D, D, wth, wtl);
    tcgemm_kernel<EPI_RES><<<dim3(D / 128, NTOK / 128), 256, TCG_SMEM>>>(
        ah, al, wth, wtl, b_proj, x, out, nullptr, nullptr,
        nullptr, nullptr, nullptr, nullptr, nullptr, nullptr, NTOK, D, D);
    // 5. rmsnorm(out, g2) -> ah/al
    rmsnorm_split_kernel<<<NTOK, 256>>>(out, g2, ah, al);
    // 6. bh/bl = gelu(h @ w_fc1 + b_fc1) split
    transpose_split_kernel<<<dim3(D4 / 32, D / 32), tp>>>(w_fc1, D, D4, wth, wtl);
    tcgemm_kernel<EPI_GELU><<<dim3(D4 / 128, NTOK / 128), 256, TCG_SMEM>>>(
        ah, al, wth, wtl, b_fc1, nullptr, nullptr, bh, bl,
        nullptr, nullptr, nullptr, nullptr, nullptr, nullptr, NTOK, D4, D);
    // 7. out = out + act @ w_fc2 + b_fc2
    transpose_split_kernel<<<dim3(D / 32, D4 / 32), tp>>>(w_fc2, D4, D, wth, wtl);
    tcgemm_kernel<EPI_RES><<<dim3(D / 128, NTOK / 128), 256, TCG_SMEM>>>(
        bh, bl, wth, wtl, b_fc2, out, out, nullptr, nullptr,
        nullptr, nullptr, nullptr, nullptr, nullptr, nullptr, NTOK, D, D4);
}